// round 7
// baseline (speedup 1.0000x reference)
#include <cuda_runtime.h>

// TransOp_expm via Cayley-Hamilton, 2 batches/thread packed f32x2.
// R7: persistent grid-stride kernel with software-prefetched loads so the
// ~600-cyc DRAM latency hides under the previous pair's compute.
// NSQ=3, ORDER=10.

#define NSQ 3
#define NORD 10

typedef unsigned long long ull;

__device__ __forceinline__ ull pk(float lo, float hi) {
    ull r; asm("mov.b64 %0, {%1, %2};" : "=l"(r) : "f"(lo), "f"(hi)); return r;
}
__device__ __forceinline__ void upk(ull v, float& lo, float& hi) {
    asm("mov.b64 {%0, %1}, %2;" : "=f"(lo), "=f"(hi) : "l"(v));
}
__device__ __forceinline__ ull fma2(ull a, ull b, ull c) {
    ull d; asm("fma.rn.f32x2 %0, %1, %2, %3;" : "=l"(d) : "l"(a), "l"(b), "l"(c)); return d;
}
__device__ __forceinline__ ull mul2(ull a, ull b) {
    ull d; asm("mul.rn.f32x2 %0, %1, %2;" : "=l"(d) : "l"(a), "l"(b)); return d;
}
__device__ __forceinline__ ull add2(ull a, ull b) {
    ull d; asm("add.rn.f32x2 %0, %1, %2;" : "=l"(d) : "l"(a), "l"(b)); return d;
}
__device__ __forceinline__ ull bcast(float v) { return pk(v, v); }

// Core: given packed cm[6] and packed v, produce packed y. Uses shared psi.
__device__ __forceinline__ void expm_core(
    const ull* __restrict__ s_psi,
    const ull cm[6], ull v0, ull v1, ull v2,
    ull& y0, ull& y1, ull& y2)
{
    ull c1, nc2, c3, k_a, k_b, k_c, c1x2, nc2x2, c3x2;
    ull w0, w1, w2, u0, u1, u2;
    {
        const ull NEG1 = bcast(-1.0f);
        ull A[9];
        {
            const ulonglong2* sv = (const ulonglong2*)s_psi;
            ulonglong2 p0 = sv[0], p1 = sv[1], p2 = sv[2], p3 = sv[3];
            ull p8 = s_psi[8];
            A[0] = mul2(cm[0], p0.x); A[1] = mul2(cm[0], p0.y);
            A[2] = mul2(cm[0], p1.x); A[3] = mul2(cm[0], p1.y);
            A[4] = mul2(cm[0], p2.x); A[5] = mul2(cm[0], p2.y);
            A[6] = mul2(cm[0], p3.x); A[7] = mul2(cm[0], p3.y);
            A[8] = mul2(cm[0], p8);
            #pragma unroll
            for (int m = 1; m < 6; m++) {
                ulonglong2 r0 = sv[m * 5 + 0], r1 = sv[m * 5 + 1];
                ulonglong2 r2 = sv[m * 5 + 2], r3 = sv[m * 5 + 3];
                ull r8 = s_psi[m * 10 + 8];
                A[0] = fma2(cm[m], r0.x, A[0]); A[1] = fma2(cm[m], r0.y, A[1]);
                A[2] = fma2(cm[m], r1.x, A[2]); A[3] = fma2(cm[m], r1.y, A[3]);
                A[4] = fma2(cm[m], r2.x, A[4]); A[5] = fma2(cm[m], r2.y, A[5]);
                A[6] = fma2(cm[m], r3.x, A[6]); A[7] = fma2(cm[m], r3.y, A[7]);
                A[8] = fma2(cm[m], r8, A[8]);
            }
        }

        c1 = add2(add2(A[0], A[4]), A[8]);
        ull d0 = fma2(A[0], A[0], fma2(A[1], A[3], mul2(A[2], A[6])));
        ull d1 = fma2(A[3], A[1], fma2(A[4], A[4], mul2(A[5], A[7])));
        ull d2 = fma2(A[6], A[2], fma2(A[7], A[5], mul2(A[8], A[8])));
        ull trA2 = add2(add2(d0, d1), d2);
        ull c1sq = mul2(c1, c1);
        nc2 = mul2(fma2(c1sq, NEG1, trA2), bcast(0.5f));           // -c2
        ull m0  = fma2(mul2(A[5], A[7]), NEG1, mul2(A[4], A[8]));
        ull m1n = fma2(mul2(A[3], A[8]), NEG1, mul2(A[5], A[6]));
        ull m2  = fma2(mul2(A[4], A[6]), NEG1, mul2(A[3], A[7]));
        c3  = fma2(A[0], m0, fma2(A[1], m1n, mul2(A[2], m2)));
        k_a = mul2(c1, c3);
        k_b = fma2(c1, nc2, c3);
        k_c = add2(c1sq, nc2);
        c1x2  = add2(c1, c1);
        nc2x2 = add2(nc2, nc2);
        c3x2  = add2(c3, c3);

        w0 = fma2(A[0], v0, fma2(A[1], v1, mul2(A[2], v2)));
        w1 = fma2(A[3], v0, fma2(A[4], v1, mul2(A[5], v2)));
        w2 = fma2(A[6], v0, fma2(A[7], v1, mul2(A[8], v2)));
        u0 = fma2(A[0], w0, fma2(A[1], w1, mul2(A[2], w2)));
        u1 = fma2(A[3], w0, fma2(A[4], w1, mul2(A[5], w2)));
        u2 = fma2(A[6], w0, fma2(A[7], w1, mul2(A[8], w2)));
    }

    const float invfact[NORD + 1] = {
        1.f, 1.f, 0.5f, 1.f/6.f, 1.f/24.f, 1.f/120.f, 1.f/720.f,
        1.f/5040.f, 1.f/40320.f, 1.f/362880.f, 1.f/3628800.f
    };
    ull sa = bcast(invfact[NORD]), sb = 0ULL, sc = 0ULL;
    #pragma unroll
    for (int k = NORD - 1; k >= 0; k--) {
        ull na  = fma2(c3,  sc, bcast(invfact[k]));
        ull nb  = fma2(nc2, sc, sa);
        ull ncc = fma2(c1,  sc, sb);
        sa = na; sb = nb; sc = ncc;
    }

    #pragma unroll
    for (int sq = 0; sq < NSQ; sq++) {
        ull bc = mul2(sb, sc);
        ull cc = mul2(sc, sc);
        ull ab = mul2(sa, sb);
        ull ac = mul2(sa, sc);
        ull na  = fma2(cc, k_a, fma2(bc, c3x2,  mul2(sa, sa)));
        ull nb  = fma2(cc, k_b, fma2(bc, nc2x2, add2(ab, ab)));
        ull ncc = fma2(cc, k_c, fma2(bc, c1x2,  fma2(sb, sb, add2(ac, ac))));
        sa = na; sb = nb; sc = ncc;
    }

    y0 = fma2(sa, v0, fma2(sb, w0, mul2(sc, u0)));
    y1 = fma2(sa, v1, fma2(sb, w1, mul2(sc, u1)));
    y2 = fma2(sa, v2, fma2(sb, w2, mul2(sc, u2)));
}

__global__ __launch_bounds__(256, 4) void expmch7_kernel(
    const float* __restrict__ x,
    const float* __restrict__ c,
    const float* __restrict__ psi,
    float* __restrict__ out,
    int B)
{
    __shared__ __align__(16) ull s_psi[60];
    if (threadIdx.x < 60) {
        int row = threadIdx.x / 10, col = threadIdx.x % 10;
        float v = (col < 9) ? psi[row * 9 + col] * (1.0f / (float)(1 << NSQ)) : 0.0f;
        s_psi[threadIdx.x] = pk(v, v);
    }
    __syncthreads();

    const int P = (B + 1) >> 1;                    // pairs
    const int stride = gridDim.x * blockDim.x;
    int p = blockIdx.x * blockDim.x + threadIdx.x;
    if (p >= P) return;

    // ---- prime: load raw data for first pair ----
    float4 q0, q1, q2; float2 f0, f1, f2;
    bool full = (2 * p + 1 < B);
    if (full) {
        const float4* cq = ((const float4*)c) + p * 3;
        q0 = __ldg(&cq[0]); q1 = __ldg(&cq[1]); q2 = __ldg(&cq[2]);
        const float2* xq = ((const float2*)x) + p * 3;
        f0 = __ldg(&xq[0]); f1 = __ldg(&xq[1]); f2 = __ldg(&xq[2]);
    } else {
        const float* cb = c + 2 * p * 6;
        q0 = make_float4(__ldg(&cb[0]), __ldg(&cb[1]), __ldg(&cb[2]), __ldg(&cb[3]));
        q1 = make_float4(__ldg(&cb[4]), __ldg(&cb[5]), 0.f, 0.f);
        q2 = make_float4(0.f, 0.f, 0.f, 0.f);
        const float* xb = x + 2 * p * 3;
        f0 = make_float2(__ldg(&xb[0]), __ldg(&xb[1]));
        f1 = make_float2(__ldg(&xb[2]), 0.f);
        f2 = make_float2(0.f, 0.f);
    }

    while (true) {
        // ---- prefetch next pair's raw data (overlaps with compute below) ----
        int pn = p + stride;
        bool has_next = (pn < P);
        float4 n0, n1, n2; float2 g0, g1, g2; bool nfull = false;
        if (has_next) {
            nfull = (2 * pn + 1 < B);
            if (nfull) {
                const float4* cq = ((const float4*)c) + pn * 3;
                n0 = __ldg(&cq[0]); n1 = __ldg(&cq[1]); n2 = __ldg(&cq[2]);
                const float2* xq = ((const float2*)x) + pn * 3;
                g0 = __ldg(&xq[0]); g1 = __ldg(&xq[1]); g2 = __ldg(&xq[2]);
            } else {
                const float* cb = c + 2 * pn * 6;
                n0 = make_float4(__ldg(&cb[0]), __ldg(&cb[1]), __ldg(&cb[2]), __ldg(&cb[3]));
                n1 = make_float4(__ldg(&cb[4]), __ldg(&cb[5]), 0.f, 0.f);
                n2 = make_float4(0.f, 0.f, 0.f, 0.f);
                const float* xb = x + 2 * pn * 3;
                g0 = make_float2(__ldg(&xb[0]), __ldg(&xb[1]));
                g1 = make_float2(__ldg(&xb[2]), 0.f);
                g2 = make_float2(0.f, 0.f);
            }
        }

        // ---- pack current pair ----
        ull cm[6], v0, v1, v2;
        if (full) {
            cm[0] = pk(q0.x, q1.z);
            cm[1] = pk(q0.y, q1.w);
            cm[2] = pk(q0.z, q2.x);
            cm[3] = pk(q0.w, q2.y);
            cm[4] = pk(q1.x, q2.z);
            cm[5] = pk(q1.y, q2.w);
            v0 = pk(f0.x, f1.y);
            v1 = pk(f0.y, f2.x);
            v2 = pk(f1.x, f2.y);
        } else {
            cm[0] = pk(q0.x, q0.x);
            cm[1] = pk(q0.y, q0.y);
            cm[2] = pk(q0.z, q0.z);
            cm[3] = pk(q0.w, q0.w);
            cm[4] = pk(q1.x, q1.x);
            cm[5] = pk(q1.y, q1.y);
            v0 = pk(f0.x, f0.x);
            v1 = pk(f0.y, f0.y);
            v2 = pk(f1.x, f1.x);
        }

        // ---- compute ----
        ull y0, y1, y2;
        expm_core(s_psi, cm, v0, v1, v2, y0, y1, y2);

        // ---- store current pair ----
        if (full) {
            float y0a, y0b, y1a, y1b, y2a, y2b;
            upk(y0, y0a, y0b); upk(y1, y1a, y1b); upk(y2, y2a, y2b);
            float2* oq = ((float2*)out) + p * 3;
            oq[0] = make_float2(y0a, y1a);
            oq[1] = make_float2(y2a, y0b);
            oq[2] = make_float2(y1b, y2b);
        } else {
            float lo, hi;
            float* ob = out + 2 * p * 3;
            upk(y0, lo, hi); ob[0] = lo;
            upk(y1, lo, hi); ob[1] = lo;
            upk(y2, lo, hi); ob[2] = lo;
        }

        if (!has_next) break;
        p = pn; full = nfull;
        q0 = n0; q1 = n1; q2 = n2;
        f0 = g0; f1 = g1; f2 = g2;
    }
}

extern "C" void kernel_launch(void* const* d_in, const int* in_sizes, int n_in,
                              void* d_out, int out_size) {
    const float* x   = (const float*)d_in[0];  // [B,3,1]
    const float* c   = (const float*)d_in[1];  // [B,6]
    const float* psi = (const float*)d_in[2];  // [6,3,3]
    float* out = (float*)d_out;                // [B,3]

    int B = in_sizes[0] / 3;
    int P = (B + 1) / 2;
    int threads = 256;
    // persistent-style: ~4 resident blocks x 148 SMs; cap at what's needed
    int blocks = 148 * 4;
    int needed = (P + threads - 1) / threads;
    if (needed < blocks) blocks = needed;
    expmch7_kernel<<<blocks, threads>>>(x, c, psi, out, B);
}

// round 8
// speedup vs baseline: 1.0115x; 1.0115x over previous
#include <cuda_runtime.h>

// TransOp_expm via traceless Cayley-Hamilton, 2 batches/thread packed f32x2.
// A = T/2^NSQ = mu*I + Abar (traceless). exp(T) = e^{trT/3} * expm(Abar)^{2^NSQ},
// with expm(Abar) = sa I + sb Abar + sc Abar^2 computed by a 2-fma/step Horner
// recurrence and 13-op coefficient-space squarings (char poly: Ab^3 = nc2*Ab + c3*I).
// NSQ=3, ORDER=10.

#define NSQ 3
#define NORD 10

typedef unsigned long long ull;

__device__ __forceinline__ ull pk(float lo, float hi) {
    ull r; asm("mov.b64 %0, {%1, %2};" : "=l"(r) : "f"(lo), "f"(hi)); return r;
}
__device__ __forceinline__ void upk(ull v, float& lo, float& hi) {
    asm("mov.b64 {%0, %1}, %2;" : "=f"(lo), "=f"(hi) : "l"(v));
}
__device__ __forceinline__ ull fma2(ull a, ull b, ull c) {
    ull d; asm("fma.rn.f32x2 %0, %1, %2, %3;" : "=l"(d) : "l"(a), "l"(b), "l"(c)); return d;
}
__device__ __forceinline__ ull mul2(ull a, ull b) {
    ull d; asm("mul.rn.f32x2 %0, %1, %2;" : "=l"(d) : "l"(a), "l"(b)); return d;
}
__device__ __forceinline__ ull add2(ull a, ull b) {
    ull d; asm("add.rn.f32x2 %0, %1, %2;" : "=l"(d) : "l"(a), "l"(b)); return d;
}
__device__ __forceinline__ ull bcast(float v) { return pk(v, v); }

__global__ __launch_bounds__(256, 6) void expmch8_kernel(
    const float* __restrict__ x,
    const float* __restrict__ c,
    const float* __restrict__ psi,
    float* __restrict__ out,
    int B)
{
    // psi pre-scaled by 1/2^NSQ, packed f32x2, rows padded to 10 ulls
    __shared__ __align__(16) ull s_psi[60];
    if (threadIdx.x < 60) {
        int row = threadIdx.x / 10, col = threadIdx.x % 10;
        float v = (col < 9) ? psi[row * 9 + col] * (1.0f / (float)(1 << NSQ)) : 0.0f;
        s_psi[threadIdx.x] = pk(v, v);
    }
    __syncthreads();

    int t  = blockIdx.x * blockDim.x + threadIdx.x;
    int b0 = 2 * t;
    if (b0 >= B) return;
    bool full = (b0 + 1 < B);

    // ---- load c and x ----
    ull cm[6];
    ull v0, v1, v2;
    if (full) {
        const float4* cq = (const float4*)(c + b0 * 6);
        float4 q0 = __ldg(&cq[0]);
        float4 q1 = __ldg(&cq[1]);
        float4 q2 = __ldg(&cq[2]);
        const float2* xq = (const float2*)(x + b0 * 3);
        float2 f0 = __ldg(&xq[0]);
        float2 f1 = __ldg(&xq[1]);
        float2 f2 = __ldg(&xq[2]);
        cm[0] = pk(q0.x, q1.z);
        cm[1] = pk(q0.y, q1.w);
        cm[2] = pk(q0.z, q2.x);
        cm[3] = pk(q0.w, q2.y);
        cm[4] = pk(q1.x, q2.z);
        cm[5] = pk(q1.y, q2.w);
        v0 = pk(f0.x, f1.y);
        v1 = pk(f0.y, f2.x);
        v2 = pk(f1.x, f2.y);
    } else {
        const float* cb = c + b0 * 6;
        #pragma unroll
        for (int m = 0; m < 6; m++) { float v = __ldg(&cb[m]); cm[m] = pk(v, v); }
        const float* xb = x + b0 * 3;
        float x0 = __ldg(&xb[0]), x1 = __ldg(&xb[1]), x2 = __ldg(&xb[2]);
        v0 = pk(x0, x0); v1 = pk(x1, x1); v2 = pk(x2, x2);
    }

    // ---- build A, shift to traceless Abar, invariants, matvecs ----
    ull nc2, c3, emu;
    ull w0, w1, w2, u0, u1, u2;
    {
        const ull NEG1 = bcast(-1.0f);
        ull A[9];
        {
            const ulonglong2* sv = (const ulonglong2*)s_psi;
            ulonglong2 p0 = sv[0], p1 = sv[1], p2 = sv[2], p3 = sv[3];
            ull p8 = s_psi[8];
            A[0] = mul2(cm[0], p0.x); A[1] = mul2(cm[0], p0.y);
            A[2] = mul2(cm[0], p1.x); A[3] = mul2(cm[0], p1.y);
            A[4] = mul2(cm[0], p2.x); A[5] = mul2(cm[0], p2.y);
            A[6] = mul2(cm[0], p3.x); A[7] = mul2(cm[0], p3.y);
            A[8] = mul2(cm[0], p8);
            #pragma unroll
            for (int m = 1; m < 6; m++) {
                ulonglong2 r0 = sv[m * 5 + 0], r1 = sv[m * 5 + 1];
                ulonglong2 r2 = sv[m * 5 + 2], r3 = sv[m * 5 + 3];
                ull r8 = s_psi[m * 10 + 8];
                A[0] = fma2(cm[m], r0.x, A[0]); A[1] = fma2(cm[m], r0.y, A[1]);
                A[2] = fma2(cm[m], r1.x, A[2]); A[3] = fma2(cm[m], r1.y, A[3]);
                A[4] = fma2(cm[m], r2.x, A[4]); A[5] = fma2(cm[m], r2.y, A[5]);
                A[6] = fma2(cm[m], r3.x, A[6]); A[7] = fma2(cm[m], r3.y, A[7]);
                A[8] = fma2(cm[m], r8, A[8]);
            }
        }

        // trace and exp-scale (MUFU pipe, issued early so latency hides)
        ull c1 = add2(add2(A[0], A[4]), A[8]);
        {
            float c1lo, c1hi;
            upk(c1, c1lo, c1hi);
            const float s = (float)(1 << NSQ) / 3.0f;   // exp(trT/3) = exp(c1 * 2^NSQ / 3)
            emu = pk(__expf(c1lo * s), __expf(c1hi * s));
        }
        // shift: Abar = A - (c1/3) I
        ull nmu = mul2(c1, bcast(-1.0f / 3.0f));
        A[0] = add2(A[0], nmu);
        A[4] = add2(A[4], nmu);
        A[8] = add2(A[8], nmu);

        // nc2 = tr(Abar^2)/2 = (sum diag^2)/2 + (A1A3 + A2A6 + A5A7)
        ull tt = fma2(A[2], A[6], mul2(A[1], A[3]));
        tt = fma2(A[5], A[7], tt);
        ull ss = fma2(A[4], A[4], mul2(A[0], A[0]));
        ss = fma2(A[8], A[8], ss);
        nc2 = fma2(ss, bcast(0.5f), tt);

        // c3 = det(Abar)
        ull m0  = fma2(mul2(A[5], A[7]), NEG1, mul2(A[4], A[8]));
        ull m1n = fma2(mul2(A[3], A[8]), NEG1, mul2(A[5], A[6]));
        ull m2  = fma2(mul2(A[4], A[6]), NEG1, mul2(A[3], A[7]));
        c3  = fma2(A[0], m0, fma2(A[1], m1n, mul2(A[2], m2)));

        // w = Abar v, u = Abar w
        w0 = fma2(A[0], v0, fma2(A[1], v1, mul2(A[2], v2)));
        w1 = fma2(A[3], v0, fma2(A[4], v1, mul2(A[5], v2)));
        w2 = fma2(A[6], v0, fma2(A[7], v1, mul2(A[8], v2)));
        u0 = fma2(A[0], w0, fma2(A[1], w1, mul2(A[2], w2)));
        u1 = fma2(A[3], w0, fma2(A[4], w1, mul2(A[5], w2)));
        u2 = fma2(A[6], w0, fma2(A[7], w1, mul2(A[8], w2)));
    }   // A dead

    // ---- Horner Taylor (traceless): E = sa I + sb Ab + sc Ab^2 ----
    // E <- Ab*E + cf*I :  a' = c3*c + cf;  b' = nc2*c + a;  c' = b
    const float invfact[NORD + 1] = {
        1.f, 1.f, 0.5f, 1.f/6.f, 1.f/24.f, 1.f/120.f, 1.f/720.f,
        1.f/5040.f, 1.f/40320.f, 1.f/362880.f, 1.f/3628800.f
    };
    ull sa = bcast(invfact[NORD]), sb = 0ULL, sc = 0ULL;
    #pragma unroll
    for (int k = NORD - 1; k >= 0; k--) {
        ull oc = sc;
        ull na = fma2(c3,  oc, bcast(invfact[k]));
        ull nb = fma2(nc2, oc, sa);
        sc = sb;
        sa = na;
        sb = nb;
    }

    // ---- NSQ squarings (traceless char poly: Ab^3 = nc2 Ab + c3 I) ----
    // E^2 = (sa^2 + 2bc*c3) I + (2ab + 2bc*nc2 + cc*c3) Ab + (sb^2 + 2ac + cc*nc2) Ab^2
    #pragma unroll
    for (int sq = 0; sq < NSQ; sq++) {
        ull bc  = mul2(sb, sc);
        ull bc2 = add2(bc, bc);
        ull cc  = mul2(sc, sc);
        ull ab  = mul2(sa, sb);
        ull ab2 = add2(ab, ab);
        ull ac  = mul2(sa, sc);
        ull ac2 = add2(ac, ac);
        ull na  = fma2(bc2, c3, mul2(sa, sa));
        ull nb  = fma2(cc, c3, fma2(bc2, nc2, ab2));
        ull ncc = fma2(cc, nc2, fma2(sb, sb, ac2));
        sa = na; sb = nb; sc = ncc;
    }

    // ---- scale by e^{trT/3} and combine: y = sa*v + sb*w + sc*u ----
    sa = mul2(sa, emu);
    sb = mul2(sb, emu);
    sc = mul2(sc, emu);
    ull y0 = fma2(sa, v0, fma2(sb, w0, mul2(sc, u0)));
    ull y1 = fma2(sa, v1, fma2(sb, w1, mul2(sc, u1)));
    ull y2 = fma2(sa, v2, fma2(sb, w2, mul2(sc, u2)));

    if (full) {
        float y0a, y0b, y1a, y1b, y2a, y2b;
        upk(y0, y0a, y0b); upk(y1, y1a, y1b); upk(y2, y2a, y2b);
        float2* oq = (float2*)(out + b0 * 3);
        oq[0] = make_float2(y0a, y1a);
        oq[1] = make_float2(y2a, y0b);
        oq[2] = make_float2(y1b, y2b);
    } else {
        float ya, yb;
        float* ob = out + b0 * 3;
        upk(y0, ya, yb); ob[0] = ya;
        upk(y1, ya, yb); ob[1] = ya;
        upk(y2, ya, yb); ob[2] = ya;
    }
}

extern "C" void kernel_launch(void* const* d_in, const int* in_sizes, int n_in,
                              void* d_out, int out_size) {
    const float* x   = (const float*)d_in[0];  // [B,3,1]
    const float* c   = (const float*)d_in[1];  // [B,6]
    const float* psi = (const float*)d_in[2];  // [6,3,3]
    float* out = (float*)d_out;                // [B,3]

    int B = in_sizes[0] / 3;
    int pairs = (B + 1) / 2;
    int threads = 256;
    int blocks = (pairs + threads - 1) / threads;
    expmch8_kernel<<<blocks, threads>>>(x, c, psi, out, B);
}